// round 8
// baseline (speedup 1.0000x reference)
#include <cuda_runtime.h>
#include <cuda_bf16.h>

// ---------------------------------------------------------------------------
// BSplineBasis: out[N,6] = cubic B-spline basis of min-max-normalized x.
// SINGLE persistent kernel, one wave (1184 blocks = 148 SMs x 8):
//   Phase 1: grid-stride min/max reduce -> last block finalizes g_norm,
//            raises g_ready; all blocks spin (residency guaranteed by
//            __launch_bounds__(256,8) and grid == 148*8).
//   Phase 2: grid-stride over 1024-pt tiles; closed-form span cubics
//            (knots compile-time), dense 24KB smem tile, TMA bulk store
//            with wait deferred to next iteration (overlapped drain).
// ---------------------------------------------------------------------------

#define GRID_P 1184
#define K13 0.33333334f   /* fp32(1/3) */
#define K23 0.6666667f    /* fp32(2/3) */
#define PTS_PER_TILE 1024
#define TILE_F4 1536      /* 1024 pts * 6 floats / 4 = 24 KB */

__device__ unsigned g_pmin[GRID_P];
__device__ unsigned g_pmax[GRID_P];
__device__ unsigned g_count = 0;            // reset by last phase-1 block
__device__ unsigned g_done  = 0;            // reset by last phase-2 block
__device__ volatile unsigned g_ready = 0;   // reset by last phase-2 block
__device__ float2   g_norm;                 // {scale, -xmin*scale}

__device__ __forceinline__ unsigned fenc(float f) {
    unsigned u = __float_as_uint(f);
    return (u & 0x80000000u) ? ~u : (u | 0x80000000u);
}
__device__ __forceinline__ float fdec(unsigned u) {
    return (u & 0x80000000u) ? __uint_as_float(u ^ 0x80000000u)
                             : __uint_as_float(~u);
}

__device__ __forceinline__ unsigned smem_u32(const void* p) {
    unsigned a;
    asm("{ .reg .u64 t; cvta.to.shared.u64 t, %1; cvt.u32.u64 %0, t; }"
        : "=r"(a) : "l"(p));
    return a;
}

// Closed-form cubic bases per span; coefficients are exact fp32 dyadics.
__device__ __forceinline__ void evalPoint(float u, float* __restrict__ o)
{
    if (u < K13) {
        float N0 = fmaf(u, -27.0f, 27.0f);  N0 = fmaf(u, N0, -9.0f);  N0 = fmaf(u, N0, 1.0f);
        float N1 = fmaf(u, 47.25f, -40.5f); N1 = fmaf(u, N1, 9.0f);   N1 = N1 * u;
        float N2 = fmaf(u, -24.75f, 13.5f); N2 = N2 * (u * u);
        float N3 = 4.5f * u * (u * u);
        o[0] = N0; o[1] = N1; o[2] = N2; o[3] = N3; o[4] = 0.0f; o[5] = 0.0f;
    } else if (u < K23) {
        float N1 = fmaf(u, -6.75f, 13.5f);   N1 = fmaf(u, N1, -9.0f);  N1 = fmaf(u, N1, 2.0f);
        float N2 = fmaf(u, 15.75f, -27.0f);  N2 = fmaf(u, N2, 13.5f);  N2 = fmaf(u, N2, -1.5f);
        float N3 = fmaf(u, -15.75f, 20.25f); N3 = fmaf(u, N3, -6.75f); N3 = fmaf(u, N3, 0.75f);
        float N4 = fmaf(u, 6.75f, -6.75f);   N4 = fmaf(u, N4, 2.25f);  N4 = fmaf(u, N4, -0.25f);
        o[0] = 0.0f; o[1] = N1; o[2] = N2; o[3] = N3; o[4] = N4; o[5] = 0.0f;
    } else {
        float w = 1.0f - u;
        float N5 = fmaf(w, -27.0f, 27.0f);  N5 = fmaf(w, N5, -9.0f);  N5 = fmaf(w, N5, 1.0f);
        float N4 = fmaf(w, 47.25f, -40.5f); N4 = fmaf(w, N4, 9.0f);   N4 = N4 * w;
        float N3 = fmaf(w, -24.75f, 13.5f); N3 = N3 * (w * w);
        float N2 = 4.5f * w * (w * w);
        o[0] = 0.0f; o[1] = 0.0f; o[2] = N2; o[3] = N3; o[4] = N4; o[5] = N5;
    }
}

__global__ void __launch_bounds__(256, 8)
bspline_fused_kernel(const float* __restrict__ x,
                     float* __restrict__ out, int n)
{
    __shared__ alignas(128) float4 tile[TILE_F4];
    __shared__ unsigned smin[8], smax[8];
    __shared__ bool is_last;

    int tid  = threadIdx.x;
    int lane = tid & 31;
    int warp = tid >> 5;

    // ===================== Phase 1: min/max reduction =====================
    {
        float lmin =  3.4e38f, lmax = -3.4e38f;
        int n4 = n >> 2;
        const float4* __restrict__ x4 = (const float4*)x;
        int stride = gridDim.x * blockDim.x;
        #pragma unroll 4
        for (int i = blockIdx.x * blockDim.x + tid; i < n4; i += stride) {
            float4 v = x4[i];
            lmin = fminf(lmin, fminf(fminf(v.x, v.y), fminf(v.z, v.w)));
            lmax = fmaxf(lmax, fmaxf(fmaxf(v.x, v.y), fmaxf(v.z, v.w)));
        }
        for (int i = n4 * 4 + blockIdx.x * blockDim.x + tid; i < n; i += stride) {
            float e = x[i];
            lmin = fminf(lmin, e); lmax = fmaxf(lmax, e);
        }

        unsigned emin = __reduce_min_sync(0xFFFFFFFFu, fenc(lmin));
        unsigned emax = __reduce_max_sync(0xFFFFFFFFu, fenc(lmax));
        if (lane == 0) { smin[warp] = emin; smax[warp] = emax; }
        __syncthreads();
        if (tid == 0) {
            #pragma unroll
            for (int i = 1; i < 8; i++) {
                emin = min(emin, smin[i]); emax = max(emax, smax[i]);
            }
            g_pmin[blockIdx.x] = emin;
            g_pmax[blockIdx.x] = emax;
            __threadfence();
            unsigned prev = atomicAdd(&g_count, 1u);
            is_last = (prev == gridDim.x - 1);
        }
        __syncthreads();

        if (is_last) {
            unsigned fmn = 0xFFFFFFFFu, fmx = 0u;
            for (int i = tid; i < (int)gridDim.x; i += blockDim.x) {
                fmn = min(fmn, __ldcg(&g_pmin[i]));
                fmx = max(fmx, __ldcg(&g_pmax[i]));
            }
            fmn = __reduce_min_sync(0xFFFFFFFFu, fmn);
            fmx = __reduce_max_sync(0xFFFFFFFFu, fmx);
            if (lane == 0) { smin[warp] = fmn; smax[warp] = fmx; }
            __syncthreads();
            if (tid == 0) {
                #pragma unroll
                for (int i = 1; i < 8; i++) {
                    fmn = min(fmn, smin[i]); fmx = max(fmx, smax[i]);
                }
                float xmin = fdec(fmn);
                float xmax = fdec(fmx);
                float scale = 1.0f / (xmax - xmin + 1e-8f);
                g_norm = make_float2(scale, -xmin * scale);
                g_count = 0;                       // all adds already done
                __threadfence();
                g_ready = 1u;                      // release
            }
        }

        // spin until norm is published (one wave guaranteed resident)
        if (tid == 0) { while (g_ready == 0u) { } }
        __syncthreads();
        __threadfence();
    }

    // ===================== Phase 2: basis evaluation ======================
    float2 nrm = g_norm;
    float scale = nrm.x, nb = nrm.y;

    int tiles = (n + PTS_PER_TILE - 1) / PTS_PER_TILE;
    for (int tIdx = blockIdx.x; tIdx < tiles; tIdx += gridDim.x) {
        int bbase = tIdx * PTS_PER_TILE;

        if (bbase + PTS_PER_TILE <= n) {
            // ensure previous tile's TMA store has consumed smem
            if (tid == 0)
                asm volatile("cp.async.bulk.wait_group 0;" ::: "memory");
            __syncthreads();

            int wbase = bbase + warp * 128;
            float4 v = ((const float4*)x)[(wbase >> 2) + lane];
            float xs[4] = {v.x, v.y, v.z, v.w};

            float res[24];
            #pragma unroll
            for (int p = 0; p < 4; p++) {
                float u = fmaf(xs[p], scale, nb);
                evalPoint(u, &res[p * 6]);
            }

            float4* ws = &tile[warp * 192 + lane * 6];
            #pragma unroll
            for (int q = 0; q < 6; q++)
                ws[q] = make_float4(res[4 * q], res[4 * q + 1],
                                    res[4 * q + 2], res[4 * q + 3]);
            __syncthreads();

            if (tid == 0) {
                asm volatile("fence.proxy.async.shared::cta;" ::: "memory");
                float* gdst = out + (size_t)bbase * 6;
                unsigned saddr = smem_u32(tile);
                asm volatile(
                    "cp.async.bulk.global.shared::cta.bulk_group [%0], [%1], %2;"
                    :: "l"(gdst), "r"(saddr), "r"((unsigned)(TILE_F4 * 16))
                    : "memory");
                asm volatile("cp.async.bulk.commit_group;" ::: "memory");
                // wait deferred to next iteration -> overlapped drain
            }
        } else {
            // tail tile: scalar per-point stores (no smem use)
            for (int p = tid; p < PTS_PER_TILE; p += blockDim.x) {
                int idx = bbase + p;
                if (idx >= n) break;
                float u = fmaf(x[idx], scale, nb);
                float b6[6];
                evalPoint(u, b6);
                float* o = out + (size_t)idx * 6;
                #pragma unroll
                for (int j = 0; j < 6; j++) o[j] = b6[j];
            }
        }
    }

    // drain outstanding bulk store, then reset flags for next graph replay
    if (tid == 0) {
        asm volatile("cp.async.bulk.wait_group 0;" ::: "memory");
        __threadfence();
        unsigned p = atomicAdd(&g_done, 1u);
        if (p == gridDim.x - 1) {
            g_done  = 0;
            g_ready = 0;
        }
    }
}

extern "C" void kernel_launch(void* const* d_in, const int* in_sizes, int n_in,
                              void* d_out, int out_size)
{
    const float* x = (const float*)d_in[0];
    float* out     = (float*)d_out;
    int n = in_sizes[0];
    if (n <= 0) return;

    bspline_fused_kernel<<<GRID_P, 256>>>(x, out, n);
}

// round 9
// speedup vs baseline: 1.1054x; 1.1054x over previous
#include <cuda_runtime.h>
#include <cuda_bf16.h>

// ---------------------------------------------------------------------------
// BSplineBasis: out[N,6] = cubic B-spline basis of min-max-normalized x.
// Knots compile-time ([0,0,0,0,1/3,2/3,1,1,1,1]) => closed-form span cubics.
// Kernel 1: min/max reduction -> g_norm = {scale, -xmin*scale}.
// Kernel 2: one wave of 592 blocks (4/SM, 48KB smem), each looping over
//           1024-pt tiles with DOUBLE-BUFFERED TMA bulk stores:
//           wait_group.read 1 before buffer reuse -> drain of tile i
//           overlaps the full compute of tile i+1 (R8's single-buffer
//           "deferred wait" overlapped nothing).
// ---------------------------------------------------------------------------

#define MAXB 1184
#define K13 0.33333334f   /* fp32(1/3) */
#define K23 0.6666667f    /* fp32(2/3) */
#define PTS_PER_TILE 1024
#define TILE_F4 1536      /* 1024 pts * 6 floats / 4 = 24 KB */
#define MGRID 592         /* 148 SMs * 4 blocks (48KB smem each) */

__device__ unsigned g_pmin[MAXB];
__device__ unsigned g_pmax[MAXB];
__device__ unsigned g_count = 0;     // restored to 0 each run (graph-safe)
__device__ float2   g_norm;          // {scale, nbias = -xmin*scale}

__device__ __forceinline__ unsigned fenc(float f) {
    unsigned u = __float_as_uint(f);
    return (u & 0x80000000u) ? ~u : (u | 0x80000000u);
}
__device__ __forceinline__ float fdec(unsigned u) {
    return (u & 0x80000000u) ? __uint_as_float(u ^ 0x80000000u)
                             : __uint_as_float(~u);
}

__global__ void __launch_bounds__(256)
reduce_setup_kernel(const float* __restrict__ x, int n)
{
    float lmin =  3.4e38f, lmax = -3.4e38f;

    int n4 = n >> 2;
    const float4* __restrict__ x4 = (const float4*)x;
    int stride = gridDim.x * blockDim.x;
    #pragma unroll 4
    for (int i = blockIdx.x * blockDim.x + threadIdx.x; i < n4; i += stride) {
        float4 v = x4[i];
        lmin = fminf(lmin, fminf(fminf(v.x, v.y), fminf(v.z, v.w)));
        lmax = fmaxf(lmax, fmaxf(fmaxf(v.x, v.y), fmaxf(v.z, v.w)));
    }
    for (int i = n4 * 4 + blockIdx.x * blockDim.x + threadIdx.x; i < n; i += stride) {
        float e = x[i];
        lmin = fminf(lmin, e); lmax = fmaxf(lmax, e);
    }

    unsigned emin = __reduce_min_sync(0xFFFFFFFFu, fenc(lmin));
    unsigned emax = __reduce_max_sync(0xFFFFFFFFu, fenc(lmax));

    __shared__ unsigned smin[8], smax[8];
    __shared__ bool is_last;
    int w = threadIdx.x >> 5;
    if ((threadIdx.x & 31) == 0) { smin[w] = emin; smax[w] = emax; }
    __syncthreads();
    if (threadIdx.x == 0) {
        int nw = blockDim.x >> 5;
        for (int i = 1; i < nw; i++) {
            emin = min(emin, smin[i]); emax = max(emax, smax[i]);
        }
        g_pmin[blockIdx.x] = emin;
        g_pmax[blockIdx.x] = emax;
        __threadfence();
        unsigned prev = atomicAdd(&g_count, 1u);
        is_last = (prev == gridDim.x - 1);
    }
    __syncthreads();
    if (!is_last) return;

    unsigned fmn = 0xFFFFFFFFu, fmx = 0u;
    int nb = gridDim.x;
    for (int i = threadIdx.x; i < nb; i += blockDim.x) {
        fmn = min(fmn, __ldcg(&g_pmin[i]));
        fmx = max(fmx, __ldcg(&g_pmax[i]));
    }
    fmn = __reduce_min_sync(0xFFFFFFFFu, fmn);
    fmx = __reduce_max_sync(0xFFFFFFFFu, fmx);
    if ((threadIdx.x & 31) == 0) { smin[w] = fmn; smax[w] = fmx; }
    __syncthreads();
    if (threadIdx.x == 0) {
        int nw = blockDim.x >> 5;
        for (int i = 1; i < nw; i++) {
            fmn = min(fmn, smin[i]); fmx = max(fmx, smax[i]);
        }
        float xmin = fdec(fmn);
        float xmax = fdec(fmx);
        float scale = 1.0f / (xmax - xmin + 1e-8f);
        g_norm = make_float2(scale, -xmin * scale);
        __threadfence();
        g_count = 0;
    }
}

// Closed-form cubic bases per span; coefficients are exact fp32 dyadics.
__device__ __forceinline__ void evalPoint(float u, float* __restrict__ o)
{
    if (u < K13) {
        float N0 = fmaf(u, -27.0f, 27.0f);  N0 = fmaf(u, N0, -9.0f);  N0 = fmaf(u, N0, 1.0f);
        float N1 = fmaf(u, 47.25f, -40.5f); N1 = fmaf(u, N1, 9.0f);   N1 = N1 * u;
        float N2 = fmaf(u, -24.75f, 13.5f); N2 = N2 * (u * u);
        float N3 = 4.5f * u * (u * u);
        o[0] = N0; o[1] = N1; o[2] = N2; o[3] = N3; o[4] = 0.0f; o[5] = 0.0f;
    } else if (u < K23) {
        float N1 = fmaf(u, -6.75f, 13.5f);   N1 = fmaf(u, N1, -9.0f);  N1 = fmaf(u, N1, 2.0f);
        float N2 = fmaf(u, 15.75f, -27.0f);  N2 = fmaf(u, N2, 13.5f);  N2 = fmaf(u, N2, -1.5f);
        float N3 = fmaf(u, -15.75f, 20.25f); N3 = fmaf(u, N3, -6.75f); N3 = fmaf(u, N3, 0.75f);
        float N4 = fmaf(u, 6.75f, -6.75f);   N4 = fmaf(u, N4, 2.25f);  N4 = fmaf(u, N4, -0.25f);
        o[0] = 0.0f; o[1] = N1; o[2] = N2; o[3] = N3; o[4] = N4; o[5] = 0.0f;
    } else {
        float w = 1.0f - u;
        float N5 = fmaf(w, -27.0f, 27.0f);  N5 = fmaf(w, N5, -9.0f);  N5 = fmaf(w, N5, 1.0f);
        float N4 = fmaf(w, 47.25f, -40.5f); N4 = fmaf(w, N4, 9.0f);   N4 = N4 * w;
        float N3 = fmaf(w, -24.75f, 13.5f); N3 = N3 * (w * w);
        float N2 = 4.5f * w * (w * w);
        o[0] = 0.0f; o[1] = 0.0f; o[2] = N2; o[3] = N3; o[4] = N4; o[5] = N5;
    }
}

__device__ __forceinline__ unsigned smem_u32(const void* p) {
    unsigned a;
    asm("{ .reg .u64 t; cvta.to.shared.u64 t, %1; cvt.u32.u64 %0, t; }"
        : "=r"(a) : "l"(p));
    return a;
}

__global__ void __launch_bounds__(256, 4)
bspline_main_kernel(const float* __restrict__ x,
                    float* __restrict__ out, int n)
{
    // 2 x 24 KB = 48 KB static smem (the full static limit)
    __shared__ alignas(128) float4 tile[2][TILE_F4];

    int tid  = threadIdx.x;
    int lane = tid & 31;
    int warp = tid >> 5;

    float2 nrm = g_norm;
    float scale = nrm.x, nb = nrm.y;

    int ntiles = (n + PTS_PER_TILE - 1) / PTS_PER_TILE;
    int k = 0;                                   // local iteration counter
    for (int tIdx = blockIdx.x; tIdx < ntiles; tIdx += gridDim.x, k++) {
        int bbase = tIdx * PTS_PER_TILE;
        int buf = k & 1;

        if (bbase + PTS_PER_TILE <= n) {
            // buffer reuse guard: allow 1 outstanding group (the other buf).
            // .read = wait only until TMA has consumed smem.
            if (k >= 2) {
                if (tid == 0)
                    asm volatile("cp.async.bulk.wait_group.read 1;" ::: "memory");
                __syncthreads();
            }

            int wbase = bbase + warp * 128;
            float4 v = ((const float4*)x)[(wbase >> 2) + lane];
            float xs[4] = {v.x, v.y, v.z, v.w};

            float res[24];
            #pragma unroll
            for (int p = 0; p < 4; p++) {
                float u = fmaf(xs[p], scale, nb);
                evalPoint(u, &res[p * 6]);
            }

            float4* ws = &tile[buf][warp * 192 + lane * 6];
            #pragma unroll
            for (int q = 0; q < 6; q++)
                ws[q] = make_float4(res[4 * q], res[4 * q + 1],
                                    res[4 * q + 2], res[4 * q + 3]);
            __syncthreads();

            if (tid == 0) {
                asm volatile("fence.proxy.async.shared::cta;" ::: "memory");
                float* gdst = out + (size_t)bbase * 6;
                unsigned saddr = smem_u32(&tile[buf][0]);
                asm volatile(
                    "cp.async.bulk.global.shared::cta.bulk_group [%0], [%1], %2;"
                    :: "l"(gdst), "r"(saddr), "r"((unsigned)(TILE_F4 * 16))
                    : "memory");
                asm volatile("cp.async.bulk.commit_group;" ::: "memory");
            }
        } else {
            // tail tile: scalar per-point stores (touches no smem buffers)
            for (int p = tid; p < PTS_PER_TILE; p += blockDim.x) {
                int idx = bbase + p;
                if (idx >= n) break;
                float u = fmaf(x[idx], scale, nb);
                float b6[6];
                evalPoint(u, b6);
                float* o = out + (size_t)idx * 6;
                #pragma unroll
                for (int j = 0; j < 6; j++) o[j] = b6[j];
            }
        }
    }

    // drain remaining bulk stores before smem is released
    if (tid == 0)
        asm volatile("cp.async.bulk.wait_group.read 0;" ::: "memory");
}

extern "C" void kernel_launch(void* const* d_in, const int* in_sizes, int n_in,
                              void* d_out, int out_size)
{
    const float* x = (const float*)d_in[0];
    float* out     = (float*)d_out;
    int n = in_sizes[0];
    if (n <= 0) return;

    int n4 = n >> 2;
    int rblocks = (n4 + 255) / 256;
    if (rblocks > MAXB) rblocks = MAXB;
    if (rblocks < 1) rblocks = 1;
    reduce_setup_kernel<<<rblocks, 256>>>(x, n);

    int ntiles = (n + PTS_PER_TILE - 1) / PTS_PER_TILE;
    int mblocks = ntiles < MGRID ? ntiles : MGRID;
    bspline_main_kernel<<<mblocks, 256>>>(x, out, n);
}

// round 10
// speedup vs baseline: 1.2163x; 1.1003x over previous
#include <cuda_runtime.h>
#include <cuda_bf16.h>

// ---------------------------------------------------------------------------
// BSplineBasis: out[N,6] = cubic B-spline basis of min-max-normalized x.
// Knots compile-time ([0,0,0,0,1/3,2/3,1,1,1,1]) => closed-form span cubics.
// Kernel 1: min/max reduction -> g_norm = {scale, -xmin*scale}.
// Kernel 2: PERSISTENT one-wave grid (1184 blocks = 148 SMs x 8), each warp
//           loops over 128-pt tiles: 4 pts/lane, polynomial eval, per-warp
//           smem transpose (stride-7 pad, conflict-free STS), then 6
//           lane-contiguous STG.128 streaming stores. No TMA (R7-R9 showed
//           it matches STG in-kernel but loses on drain overhead), no
//           cross-block sync; wave-transition overhead eliminated.
// ---------------------------------------------------------------------------

#define MAXB 1184
#define K13 0.33333334f   /* fp32(1/3) */
#define K23 0.6666667f    /* fp32(2/3) */
#define MGRID 1184        /* one wave: 148 SMs x 8 blocks */

__device__ unsigned g_pmin[MAXB];
__device__ unsigned g_pmax[MAXB];
__device__ unsigned g_count = 0;     // restored to 0 each run (graph-safe)
__device__ float2   g_norm;          // {scale, nbias = -xmin*scale}

__device__ __forceinline__ unsigned fenc(float f) {
    unsigned u = __float_as_uint(f);
    return (u & 0x80000000u) ? ~u : (u | 0x80000000u);
}
__device__ __forceinline__ float fdec(unsigned u) {
    return (u & 0x80000000u) ? __uint_as_float(u ^ 0x80000000u)
                             : __uint_as_float(~u);
}

__global__ void __launch_bounds__(256)
reduce_setup_kernel(const float* __restrict__ x, int n)
{
    float lmin =  3.4e38f, lmax = -3.4e38f;

    int n4 = n >> 2;
    const float4* __restrict__ x4 = (const float4*)x;
    int stride = gridDim.x * blockDim.x;
    #pragma unroll 4
    for (int i = blockIdx.x * blockDim.x + threadIdx.x; i < n4; i += stride) {
        float4 v = x4[i];
        lmin = fminf(lmin, fminf(fminf(v.x, v.y), fminf(v.z, v.w)));
        lmax = fmaxf(lmax, fmaxf(fmaxf(v.x, v.y), fmaxf(v.z, v.w)));
    }
    for (int i = n4 * 4 + blockIdx.x * blockDim.x + threadIdx.x; i < n; i += stride) {
        float e = x[i];
        lmin = fminf(lmin, e); lmax = fmaxf(lmax, e);
    }

    unsigned emin = __reduce_min_sync(0xFFFFFFFFu, fenc(lmin));
    unsigned emax = __reduce_max_sync(0xFFFFFFFFu, fenc(lmax));

    __shared__ unsigned smin[8], smax[8];
    __shared__ bool is_last;
    int w = threadIdx.x >> 5;
    if ((threadIdx.x & 31) == 0) { smin[w] = emin; smax[w] = emax; }
    __syncthreads();
    if (threadIdx.x == 0) {
        int nw = blockDim.x >> 5;
        for (int i = 1; i < nw; i++) {
            emin = min(emin, smin[i]); emax = max(emax, smax[i]);
        }
        g_pmin[blockIdx.x] = emin;
        g_pmax[blockIdx.x] = emax;
        __threadfence();
        unsigned prev = atomicAdd(&g_count, 1u);
        is_last = (prev == gridDim.x - 1);
    }
    __syncthreads();
    if (!is_last) return;

    unsigned fmn = 0xFFFFFFFFu, fmx = 0u;
    int nb = gridDim.x;
    for (int i = threadIdx.x; i < nb; i += blockDim.x) {
        fmn = min(fmn, __ldcg(&g_pmin[i]));
        fmx = max(fmx, __ldcg(&g_pmax[i]));
    }
    fmn = __reduce_min_sync(0xFFFFFFFFu, fmn);
    fmx = __reduce_max_sync(0xFFFFFFFFu, fmx);
    if ((threadIdx.x & 31) == 0) { smin[w] = fmn; smax[w] = fmx; }
    __syncthreads();
    if (threadIdx.x == 0) {
        int nw = blockDim.x >> 5;
        for (int i = 1; i < nw; i++) {
            fmn = min(fmn, smin[i]); fmx = max(fmx, smax[i]);
        }
        float xmin = fdec(fmn);
        float xmax = fdec(fmx);
        float scale = 1.0f / (xmax - xmin + 1e-8f);
        g_norm = make_float2(scale, -xmin * scale);
        __threadfence();
        g_count = 0;
    }
}

// Closed-form cubic bases per span; coefficients are exact fp32 dyadics.
__device__ __forceinline__ void evalPoint(float u, float* __restrict__ o)
{
    if (u < K13) {
        float N0 = fmaf(u, -27.0f, 27.0f);  N0 = fmaf(u, N0, -9.0f);  N0 = fmaf(u, N0, 1.0f);
        float N1 = fmaf(u, 47.25f, -40.5f); N1 = fmaf(u, N1, 9.0f);   N1 = N1 * u;
        float N2 = fmaf(u, -24.75f, 13.5f); N2 = N2 * (u * u);
        float N3 = 4.5f * u * (u * u);
        o[0] = N0; o[1] = N1; o[2] = N2; o[3] = N3; o[4] = 0.0f; o[5] = 0.0f;
    } else if (u < K23) {
        float N1 = fmaf(u, -6.75f, 13.5f);   N1 = fmaf(u, N1, -9.0f);  N1 = fmaf(u, N1, 2.0f);
        float N2 = fmaf(u, 15.75f, -27.0f);  N2 = fmaf(u, N2, 13.5f);  N2 = fmaf(u, N2, -1.5f);
        float N3 = fmaf(u, -15.75f, 20.25f); N3 = fmaf(u, N3, -6.75f); N3 = fmaf(u, N3, 0.75f);
        float N4 = fmaf(u, 6.75f, -6.75f);   N4 = fmaf(u, N4, 2.25f);  N4 = fmaf(u, N4, -0.25f);
        o[0] = 0.0f; o[1] = N1; o[2] = N2; o[3] = N3; o[4] = N4; o[5] = 0.0f;
    } else {
        float w = 1.0f - u;
        float N5 = fmaf(w, -27.0f, 27.0f);  N5 = fmaf(w, N5, -9.0f);  N5 = fmaf(w, N5, 1.0f);
        float N4 = fmaf(w, 47.25f, -40.5f); N4 = fmaf(w, N4, 9.0f);   N4 = N4 * w;
        float N3 = fmaf(w, -24.75f, 13.5f); N3 = N3 * (w * w);
        float N2 = 4.5f * w * (w * w);
        o[0] = 0.0f; o[1] = 0.0f; o[2] = N2; o[3] = N3; o[4] = N4; o[5] = N5;
    }
}

// Per-warp staging: 32 lanes x 6 float4, padded to stride 7 per lane.
// Write (L = 6*lane + q -> slot 7*lane + q): conflict-free.
// Read  (L = q*32 + lane -> slot L + L/6): near-linear, rare 2-way.
#define WSTAGE 224

__global__ void __launch_bounds__(256, 8)
bspline_main_kernel(const float* __restrict__ x,
                    float* __restrict__ out, int n)
{
    __shared__ float4 stage[8][WSTAGE];

    int lane = threadIdx.x & 31;
    int warp = threadIdx.x >> 5;

    float2 nrm = g_norm;
    float scale = nrm.x, nb = nrm.y;

    int totalWarps = gridDim.x * 8;
    int gwarp0 = blockIdx.x * 8 + warp;
    int nwt = (n + 127) >> 7;               // 128-pt warp-tiles
    float4* ws = stage[warp];

    for (int wt = gwarp0; wt < nwt; wt += totalWarps) {
        int wbase = wt * 128;

        if (wbase + 128 <= n) {
            // lane handles points wbase + 4*lane .. +3 (coalesced LDG.128)
            float4 v = ((const float4*)x)[(wbase >> 2) + lane];
            float xs[4] = {v.x, v.y, v.z, v.w};

            float res[24];
            #pragma unroll
            for (int p = 0; p < 4; p++) {
                float u = fmaf(xs[p], scale, nb);
                evalPoint(u, &res[p * 6]);
            }

            __syncwarp();     // previous iteration's reads done before overwrite
            #pragma unroll
            for (int q = 0; q < 6; q++)
                ws[7 * lane + q] = make_float4(res[4 * q], res[4 * q + 1],
                                               res[4 * q + 2], res[4 * q + 3]);
            __syncwarp();

            // coalesced streaming stores: 6 x STG.128, 16-B lane stride
            float4* o4 = (float4*)out + (size_t)wbase * 6 / 4;
            #pragma unroll
            for (int q = 0; q < 6; q++) {
                int L = q * 32 + lane;
                __stcs(o4 + L, ws[L + L / 6]);
            }
        } else {
            // tail warp-tile: scalar per-point
            for (int p = lane; p < 128; p += 32) {
                int idx = wbase + p;
                if (idx >= n) break;
                float u = fmaf(x[idx], scale, nb);
                float b6[6];
                evalPoint(u, b6);
                float* o = out + (size_t)idx * 6;
                #pragma unroll
                for (int j = 0; j < 6; j++) o[j] = b6[j];
            }
        }
    }
}

extern "C" void kernel_launch(void* const* d_in, const int* in_sizes, int n_in,
                              void* d_out, int out_size)
{
    const float* x = (const float*)d_in[0];
    float* out     = (float*)d_out;
    int n = in_sizes[0];
    if (n <= 0) return;

    int n4 = n >> 2;
    int rblocks = (n4 + 255) / 256;
    if (rblocks > MAXB) rblocks = MAXB;
    if (rblocks < 1) rblocks = 1;
    reduce_setup_kernel<<<rblocks, 256>>>(x, n);

    int nwt = (n + 127) >> 7;
    int mblocks = (nwt + 7) / 8;
    if (mblocks > MGRID) mblocks = MGRID;
    bspline_main_kernel<<<mblocks, 256>>>(x, out, n);
}

// round 11
// speedup vs baseline: 1.3279x; 1.0918x over previous
#include <cuda_runtime.h>
#include <cuda_bf16.h>

// ---------------------------------------------------------------------------
// BSplineBasis: out[N,6] = cubic B-spline basis of min-max-normalized x.
// Knots compile-time ([0,0,0,0,1/3,2/3,1,1,1,1]) => closed-form span cubics.
// Kernel 1: min/max reduction -> g_norm = {scale, -xmin*scale}.
// Kernel 2 (R5 structure, best measured): one-shot grid 8192, 4 pts/thread,
//   per-warp smem transpose (stride-7 pad), 6 lane-contiguous STG.128.
//   NEW: launched with PDL — x loads issued BEFORE
//   cudaGridDependencySynchronize(), overlapping the reduce kernel's tail
//   and the launch gap (R10 showed persistent grids hurt; waves are fine).
// ---------------------------------------------------------------------------

#define MAXB 1184
#define K13 0.33333334f   /* fp32(1/3) */
#define K23 0.6666667f    /* fp32(2/3) */

__device__ unsigned g_pmin[MAXB];
__device__ unsigned g_pmax[MAXB];
__device__ unsigned g_count = 0;     // restored to 0 each run (graph-safe)
__device__ float2   g_norm;          // {scale, nbias = -xmin*scale}

__device__ __forceinline__ unsigned fenc(float f) {
    unsigned u = __float_as_uint(f);
    return (u & 0x80000000u) ? ~u : (u | 0x80000000u);
}
__device__ __forceinline__ float fdec(unsigned u) {
    return (u & 0x80000000u) ? __uint_as_float(u ^ 0x80000000u)
                             : __uint_as_float(~u);
}

__global__ void __launch_bounds__(256)
reduce_setup_kernel(const float* __restrict__ x, int n)
{
    float lmin =  3.4e38f, lmax = -3.4e38f;

    int n4 = n >> 2;
    const float4* __restrict__ x4 = (const float4*)x;
    int stride = gridDim.x * blockDim.x;
    #pragma unroll 4
    for (int i = blockIdx.x * blockDim.x + threadIdx.x; i < n4; i += stride) {
        float4 v = x4[i];
        lmin = fminf(lmin, fminf(fminf(v.x, v.y), fminf(v.z, v.w)));
        lmax = fmaxf(lmax, fmaxf(fmaxf(v.x, v.y), fmaxf(v.z, v.w)));
    }
    for (int i = n4 * 4 + blockIdx.x * blockDim.x + threadIdx.x; i < n; i += stride) {
        float e = x[i];
        lmin = fminf(lmin, e); lmax = fmaxf(lmax, e);
    }

    unsigned emin = __reduce_min_sync(0xFFFFFFFFu, fenc(lmin));
    unsigned emax = __reduce_max_sync(0xFFFFFFFFu, fenc(lmax));

    __shared__ unsigned smin[8], smax[8];
    __shared__ bool is_last;
    int w = threadIdx.x >> 5;
    if ((threadIdx.x & 31) == 0) { smin[w] = emin; smax[w] = emax; }
    __syncthreads();
    if (threadIdx.x == 0) {
        int nw = blockDim.x >> 5;
        for (int i = 1; i < nw; i++) {
            emin = min(emin, smin[i]); emax = max(emax, smax[i]);
        }
        g_pmin[blockIdx.x] = emin;
        g_pmax[blockIdx.x] = emax;
        __threadfence();
        unsigned prev = atomicAdd(&g_count, 1u);
        is_last = (prev == gridDim.x - 1);
    }
    __syncthreads();
    if (!is_last) return;

    unsigned fmn = 0xFFFFFFFFu, fmx = 0u;
    int nb = gridDim.x;
    for (int i = threadIdx.x; i < nb; i += blockDim.x) {
        fmn = min(fmn, __ldcg(&g_pmin[i]));
        fmx = max(fmx, __ldcg(&g_pmax[i]));
    }
    fmn = __reduce_min_sync(0xFFFFFFFFu, fmn);
    fmx = __reduce_max_sync(0xFFFFFFFFu, fmx);
    if ((threadIdx.x & 31) == 0) { smin[w] = fmn; smax[w] = fmx; }
    __syncthreads();
    if (threadIdx.x == 0) {
        int nw = blockDim.x >> 5;
        for (int i = 1; i < nw; i++) {
            fmn = min(fmn, smin[i]); fmx = max(fmx, smax[i]);
        }
        float xmin = fdec(fmn);
        float xmax = fdec(fmx);
        float scale = 1.0f / (xmax - xmin + 1e-8f);
        g_norm = make_float2(scale, -xmin * scale);
        __threadfence();
        g_count = 0;
    }
}

// Closed-form cubic bases per span; coefficients are exact fp32 dyadics.
__device__ __forceinline__ void evalPoint(float u, float* __restrict__ o)
{
    if (u < K13) {
        float N0 = fmaf(u, -27.0f, 27.0f);  N0 = fmaf(u, N0, -9.0f);  N0 = fmaf(u, N0, 1.0f);
        float N1 = fmaf(u, 47.25f, -40.5f); N1 = fmaf(u, N1, 9.0f);   N1 = N1 * u;
        float N2 = fmaf(u, -24.75f, 13.5f); N2 = N2 * (u * u);
        float N3 = 4.5f * u * (u * u);
        o[0] = N0; o[1] = N1; o[2] = N2; o[3] = N3; o[4] = 0.0f; o[5] = 0.0f;
    } else if (u < K23) {
        float N1 = fmaf(u, -6.75f, 13.5f);   N1 = fmaf(u, N1, -9.0f);  N1 = fmaf(u, N1, 2.0f);
        float N2 = fmaf(u, 15.75f, -27.0f);  N2 = fmaf(u, N2, 13.5f);  N2 = fmaf(u, N2, -1.5f);
        float N3 = fmaf(u, -15.75f, 20.25f); N3 = fmaf(u, N3, -6.75f); N3 = fmaf(u, N3, 0.75f);
        float N4 = fmaf(u, 6.75f, -6.75f);   N4 = fmaf(u, N4, 2.25f);  N4 = fmaf(u, N4, -0.25f);
        o[0] = 0.0f; o[1] = N1; o[2] = N2; o[3] = N3; o[4] = N4; o[5] = 0.0f;
    } else {
        float w = 1.0f - u;
        float N5 = fmaf(w, -27.0f, 27.0f);  N5 = fmaf(w, N5, -9.0f);  N5 = fmaf(w, N5, 1.0f);
        float N4 = fmaf(w, 47.25f, -40.5f); N4 = fmaf(w, N4, 9.0f);   N4 = N4 * w;
        float N3 = fmaf(w, -24.75f, 13.5f); N3 = N3 * (w * w);
        float N2 = 4.5f * w * (w * w);
        o[0] = 0.0f; o[1] = 0.0f; o[2] = N2; o[3] = N3; o[4] = N4; o[5] = N5;
    }
}

// Per-warp staging: 32 lanes x 6 float4, padded to stride 7 per lane.
// Write (L = 6*lane + q -> slot 7*lane + q): conflict-free.
// Read  (L = q*32 + lane -> slot L + L/6): near-linear, rare 2-way.
#define WSTAGE 224

__global__ void __launch_bounds__(256)
bspline_main_kernel(const float* __restrict__ x,
                    float* __restrict__ out, int n)
{
    __shared__ float4 stage[8][WSTAGE];

    int lane = threadIdx.x & 31;
    int warp = threadIdx.x >> 5;
    int gwarp = blockIdx.x * 8 + warp;
    int wbase = gwarp * 128;             // first point of this warp

    if (wbase >= n) {
        cudaGridDependencySynchronize();
        return;
    }

    if (wbase + 128 <= n) {
        // Issue the x load BEFORE the dependency sync: it does not depend on
        // the reduction result, so it overlaps the reduce kernel's tail.
        float4 v = __ldg(((const float4*)x) + (wbase >> 2) + lane);

        cudaGridDependencySynchronize();      // g_norm now valid
        float2 nrm = g_norm;
        float scale = nrm.x, nb = nrm.y;

        float xs[4] = {v.x, v.y, v.z, v.w};
        float res[24];
        #pragma unroll
        for (int p = 0; p < 4; p++) {
            float u = fmaf(xs[p], scale, nb);
            evalPoint(u, &res[p * 6]);
        }

        float4* ws = stage[warp];
        #pragma unroll
        for (int q = 0; q < 6; q++)
            ws[7 * lane + q] = make_float4(res[4 * q], res[4 * q + 1],
                                           res[4 * q + 2], res[4 * q + 3]);
        __syncwarp();

        // coalesced streaming stores: 6 x STG.128, 16-B lane stride
        float4* o4 = (float4*)out + (size_t)wbase * 6 / 4;
        #pragma unroll
        for (int q = 0; q < 6; q++) {
            int L = q * 32 + lane;
            __stcs(o4 + L, ws[L + L / 6]);
        }
    } else {
        cudaGridDependencySynchronize();
        float2 nrm = g_norm;
        float scale = nrm.x, nb = nrm.y;
        // tail warp: scalar per-point
        for (int p = lane; p < 128; p += 32) {
            int idx = wbase + p;
            if (idx >= n) break;
            float u = fmaf(x[idx], scale, nb);
            float b6[6];
            evalPoint(u, b6);
            float* o = out + (size_t)idx * 6;
            #pragma unroll
            for (int j = 0; j < 6; j++) o[j] = b6[j];
        }
    }
}

extern "C" void kernel_launch(void* const* d_in, const int* in_sizes, int n_in,
                              void* d_out, int out_size)
{
    const float* x = (const float*)d_in[0];
    float* out     = (float*)d_out;
    int n = in_sizes[0];
    if (n <= 0) return;

    int n4 = n >> 2;
    int rblocks = (n4 + 255) / 256;
    if (rblocks > MAXB) rblocks = MAXB;
    if (rblocks < 1) rblocks = 1;
    reduce_setup_kernel<<<rblocks, 256>>>(x, n);

    int npts_per_block = 1024;           // 8 warps * 128 pts
    int mblocks = (n + npts_per_block - 1) / npts_per_block;

    // PDL launch: main kernel may begin before reduce fully completes;
    // cudaGridDependencySynchronize() inside provides the ordering.
    cudaLaunchConfig_t cfg = {};
    cfg.gridDim  = dim3((unsigned)mblocks);
    cfg.blockDim = dim3(256);
    cfg.dynamicSmemBytes = 0;
    cfg.stream = 0;
    cudaLaunchAttribute attr[1];
    attr[0].id = cudaLaunchAttributeProgrammaticStreamSerialization;
    attr[0].val.programmaticStreamSerializationAllowed = 1;
    cfg.attrs = attr;
    cfg.numAttrs = 1;
    cudaError_t err = cudaLaunchKernelEx(&cfg, bspline_main_kernel, x, out, n);
    if (err != cudaSuccess) {
        // fallback: plain serialized launch
        bspline_main_kernel<<<mblocks, 256>>>(x, out, n);
    }
}